// round 4
// baseline (speedup 1.0000x reference)
#include <cuda_runtime.h>

#define RSPLIT   16
#define ROWS     32            // 512 / RSPLIT rows per CTA
#define NB       160           // 5*32 boxes per batch
#define NT       256
#define NCTAS    (64 * RSPLIT)

// Per-(batch, segment) partials: [pred_sum, painted_sigmoid_sum, painted_count]
__device__ float    g_part[64][RSPLIT][4];
__device__ unsigned g_count = 0;   // last-block-done counter (self-resetting)

__device__ __forceinline__ float sigf(float x) {
    return __fdividef(1.0f, 1.0f + __expf(-x));   // EX2 + RCP
}

__global__ void __launch_bounds__(NT, 5)
mml_fused(const float* __restrict__ pred, const int* __restrict__ tgt,
          float* __restrict__ out)
{
    const int b    = blockIdx.x;      // batch
    const int seg  = blockIdx.y;      // row segment
    const int row0 = seg * ROWS;
    const int tid  = threadIdx.x;
    const int lane = tid & 31;
    const int warp = tid >> 5;

    __shared__ int4     cbox[NB];          // compacted boxes: (r0loc, r1loc, y1, y2)
    __shared__ int      s_nbox;
    __shared__ unsigned mask[ROWS * 16];   // 512 column-bits per row
    __shared__ float    red[3][NT / 32];
    __shared__ float    shl[64];
    __shared__ bool     isLast;

    if (tid == 0) s_nbox = 0;
    __syncthreads();

    // ---- compact boxes intersecting this 32-row segment ----
    const int4* tb = (const int4*)(tgt + (size_t)b * NB * 4);
    if (tid < NB) {
        int4 bx = tb[tid];
        int x1 = min(bx.x, 512),        y1 = min(bx.y, 512);
        int x2 = min(bx.x + bx.z, 512), y2 = min(bx.y + bx.w, 512);
        if (x2 > row0 && x1 < row0 + ROWS && y2 > y1) {
            int slot = atomicAdd(&s_nbox, 1);
            cbox[slot] = make_int4(max(x1 - row0, 0), min(x2 - row0, ROWS), y1, y2);
        }
    }
    __syncthreads();
    const int nbox = s_nbox;

    // ---- register paint: thread exclusively owns word (tid&15) of rows {2q, 2q+1},
    //      q = tid>>4. No atomics, no RMW. Painted count taken here via popc (exact),
    //      so the streaming loop never touches cnt.
    float cntf;
    {
        const int w       = tid & 15;
        const int r0row   = (tid >> 4) * 2;
        const int colBase = w * 32;
        unsigned m0 = 0, m1 = 0;
        for (int i = 0; i < nbox; i++) {
            int4 bx = cbox[i];                       // LDS.128 broadcast
            int lo = min(max(bx.z - colBase, 0), 32);
            int hi = min(max(bx.w - colBase, 0), 32);
            unsigned bits = (unsigned)((1ull << hi) - (1ull << lo));
            m0 |= (r0row     >= bx.x && r0row     < bx.y) ? bits : 0u;
            m1 |= (r0row + 1 >= bx.x && r0row + 1 < bx.y) ? bits : 0u;
        }
        mask[(r0row    ) * 16 + w] = m0;
        mask[(r0row + 1) * 16 + w] = m1;
        cntf = (float)(__popc(m0) + __popc(m1));
    }
    __syncthreads();

    // ---- streaming reduction over this CTA's 32x512 tile ----
    // idx strides by 256; 256 % 128 == 0 -> column position is loop-invariant.
    float psum = 0.f, isum = 0.f;
    const float4* p = (const float4*)(pred + ((size_t)b * 512 + row0) * 512);
    const int c4   = tid & 127;
    const int wofs = c4 >> 3;
    const int msh  = (c4 & 7) * 4;
    int r = tid >> 7;                         // 0 or 1; +2 per iteration
    #pragma unroll 4
    for (int k = 0; k < ROWS * 512 / 4 / NT; k++) {
        float4 v = p[tid + NT * k];
        float s0 = sigf(v.x), s1 = sigf(v.y), s2 = sigf(v.z), s3 = sigf(v.w);
        psum += (s0 + s1) + (s2 + s3);
        unsigned mw = (mask[r * 16 + wofs] >> msh) & 0xFu;
        if (mw & 1u) isum += s0;
        if (mw & 2u) isum += s1;
        if (mw & 4u) isum += s2;
        if (mw & 8u) isum += s3;
        r += 2;
    }

    // ---- block reduce ----
    #pragma unroll
    for (int off = 16; off; off >>= 1) {
        psum += __shfl_down_sync(0xffffffffu, psum, off);
        isum += __shfl_down_sync(0xffffffffu, isum, off);
        cntf += __shfl_down_sync(0xffffffffu, cntf, off);
    }
    if (lane == 0) { red[0][warp] = psum; red[1][warp] = isum; red[2][warp] = cntf; }
    __syncthreads();
    if (tid == 0) {
        float P = 0.f, I = 0.f, C = 0.f;
        #pragma unroll
        for (int w = 0; w < NT / 32; w++) { P += red[0][w]; I += red[1][w]; C += red[2][w]; }
        g_part[b][seg][0] = P;
        g_part[b][seg][1] = I;
        g_part[b][seg][2] = C;
        __threadfence();
        unsigned prev = atomicAdd(&g_count, 1u);
        isLast = (prev == NCTAS - 1);
        if (isLast) g_count = 0;               // self-reset for graph replay
    }
    __syncthreads();

    // ---- last CTA performs the final reduction ----
    if (isLast) {
        __threadfence();
        if (tid < 64) {
            volatile float* gp = (volatile float*)g_part;
            float P = 0.f, I = 0.f, C = 0.f;
            for (int s = 0; s < RSPLIT; s++) {
                P += gp[(tid * RSPLIT + s) * 4 + 0];
                I += gp[(tid * RSPLIT + s) * 4 + 1];
                C += gp[(tid * RSPLIT + s) * 4 + 2];
            }
            float inter = 255.f * I;
            shl[tid] = (inter + 1.f) / (P + 255.f * C - inter + 1.f);
        }
        __syncthreads();
        #pragma unroll
        for (int off = 32; off; off >>= 1) {
            if (tid < off && tid + off < 64) shl[tid] += shl[tid + off];
            __syncthreads();
        }
        if (tid == 0) out[0] = 1.0f - shl[0] * (1.0f / 64.0f);
    }
}

extern "C" void kernel_launch(void* const* d_in, const int* in_sizes, int n_in,
                              void* d_out, int out_size) {
    const float* pred = (const float*)d_in[0];   // (64,1,512,512) fp32
    const int*   tgt  = (const int*)d_in[1];     // (64,5,32,4) int32
    float* out = (float*)d_out;                  // scalar

    dim3 grid(64, RSPLIT);
    mml_fused<<<grid, NT>>>(pred, tgt, out);
}